// round 1
// baseline (speedup 1.0000x reference)
#include <cuda_runtime.h>
#include <cuda_bf16.h>

#define DIM 128
#define NMAX 50000
#define BN_EPS 1e-5f

// Scratch: two ping-pong node-feature buffers (25.6 MB each). Static __device__
// arrays per the allocation-free rules.
__device__ float g_buf0[NMAX * DIM];
__device__ float g_buf1[NMAX * DIM];

// ---------------------------------------------------------------------------
// Copy h -> agg (initializes the (1+eps)*h term of GIN with eps=0)
// ---------------------------------------------------------------------------
__global__ void copy_kernel(const float* __restrict__ in, float* __restrict__ out, int n4) {
    int i = blockIdx.x * blockDim.x + threadIdx.x;
    if (i < n4) {
        ((float4*)out)[i] = ((const float4*)in)[i];
    }
}

// ---------------------------------------------------------------------------
// Edge scatter: agg[dst] += h[src].  One warp per edge, lane handles 4 cols.
// float atomicAdd with unused return -> REDG (no round trip).
// ---------------------------------------------------------------------------
__global__ void scatter_kernel(const float* __restrict__ h,
                               const int* __restrict__ src,
                               const int* __restrict__ dst,
                               float* __restrict__ agg, int nedges) {
    int t = blockIdx.x * blockDim.x + threadIdx.x;
    int e = t >> 5;
    int lane = t & 31;
    if (e >= nedges) return;
    int s = __ldg(src + e);
    int d = __ldg(dst + e);
    float4 v = *(const float4*)(h + (size_t)s * DIM + lane * 4);
    float* p = agg + (size_t)d * DIM + lane * 4;
    atomicAdd(p + 0, v.x);
    atomicAdd(p + 1, v.y);
    atomicAdd(p + 2, v.z);
    atomicAdd(p + 3, v.w);
}

// ---------------------------------------------------------------------------
// Fused GEMM + bias + BatchNorm(eval) + ReLU.
//   out[n, j] = relu( (sum_k A[n,k] * W[k,j] + bias[j]) * scale[j] + shift[j] )
//   scale = gamma * rsqrt(var + eps); shift = beta - mean * scale
//
// Block: 256 threads, 64 rows. W (128x128, 64KB) + H tile (64x128, 32KB) in
// dynamic smem (96KB -> 2 blocks/SM). Thread (col = tid&127, half = tid>>7)
// accumulates 32 rows. Inner loop: 1 LDS.128 (broadcast) per 4 FFMA, W reads
// bank-conflict-free -> FMA-pipe bound.
// ---------------------------------------------------------------------------
__global__ void __launch_bounds__(256, 2)
gemm_bn_relu_kernel(const float* __restrict__ A,
                    const float* __restrict__ W,
                    const float* __restrict__ bias,
                    const float* __restrict__ gamma,
                    const float* __restrict__ beta,
                    const float* __restrict__ mean,
                    const float* __restrict__ var,
                    float* __restrict__ out, int nrows) {
    extern __shared__ float sm[];
    float* Ws = sm;               // 128*128
    float* Hs = sm + DIM * DIM;   // 64*128

    int tid = threadIdx.x;

    // Stage W (16384 floats = 4096 float4)
    const float4* W4 = (const float4*)W;
    float4* Ws4 = (float4*)Ws;
#pragma unroll
    for (int i = tid; i < DIM * (DIM / 4); i += 256) {
        Ws4[i] = W4[i];
    }

    // Stage H tile (64 rows x 128 cols = 2048 float4), zero-pad past nrows
    int row0 = blockIdx.x * 64;
    float4* Hs4 = (float4*)Hs;
    for (int i = tid; i < 64 * (DIM / 4); i += 256) {
        int r = i >> 5;
        int row = row0 + r;
        float4 v = make_float4(0.f, 0.f, 0.f, 0.f);
        if (row < nrows) {
            v = ((const float4*)(A + (size_t)row * DIM))[i & 31];
        }
        Hs4[i] = v;
    }
    __syncthreads();

    int col = tid & 127;
    int half = tid >> 7;
    const float* hb = Hs + half * 32 * DIM;

    float acc[32];
#pragma unroll
    for (int r = 0; r < 32; r++) acc[r] = 0.f;

#pragma unroll 8
    for (int k = 0; k < DIM; k += 4) {
        float w0 = Ws[(k + 0) * DIM + col];
        float w1 = Ws[(k + 1) * DIM + col];
        float w2 = Ws[(k + 2) * DIM + col];
        float w3 = Ws[(k + 3) * DIM + col];
#pragma unroll
        for (int r = 0; r < 32; r++) {
            float4 h4 = *(const float4*)(hb + r * DIM + k);
            acc[r] = fmaf(h4.w, w3, fmaf(h4.z, w2, fmaf(h4.y, w1, fmaf(h4.x, w0, acc[r]))));
        }
    }

    // Epilogue: bias + folded BN + ReLU
    float b  = bias[col];
    float sc = gamma[col] * rsqrtf(var[col] + BN_EPS);
    float sh = beta[col] - mean[col] * sc;
    int rbase = row0 + half * 32;
#pragma unroll
    for (int r = 0; r < 32; r++) {
        int row = rbase + r;
        if (row < nrows) {
            float z = (acc[r] + b) * sc + sh;
            out[(size_t)row * DIM + col] = fmaxf(z, 0.f);
        }
    }
}

// ---------------------------------------------------------------------------
// Launch
// Inputs (metadata order): x[N,128], edge_index[2,E], W1[3,128,128], b1[3,128],
// W2[3,128,128], b2[3,128], g[3,2,128], be[3,2,128], rm[3,2,128], rv[3,2,128]
// ---------------------------------------------------------------------------
extern "C" void kernel_launch(void* const* d_in, const int* in_sizes, int n_in,
                              void* d_out, int out_size) {
    const float* x   = (const float*)d_in[0];
    const int*   ei  = (const int*)d_in[1];
    const float* W1  = (const float*)d_in[2];
    const float* b1  = (const float*)d_in[3];
    const float* W2  = (const float*)d_in[4];
    const float* b2  = (const float*)d_in[5];
    const float* g   = (const float*)d_in[6];
    const float* be  = (const float*)d_in[7];
    const float* rm  = (const float*)d_in[8];
    const float* rv  = (const float*)d_in[9];

    int N = in_sizes[0] / DIM;
    int E = in_sizes[1] / 2;
    const int* src = ei;
    const int* dst = ei + E;

    float* out = (float*)d_out;

    float* buf0 = nullptr;
    float* buf1 = nullptr;
    cudaGetSymbolAddress((void**)&buf0, g_buf0);
    cudaGetSymbolAddress((void**)&buf1, g_buf1);

    const int SMEM = (DIM * DIM + 64 * DIM) * (int)sizeof(float);  // 96 KB
    cudaFuncSetAttribute(gemm_bn_relu_kernel,
                         cudaFuncAttributeMaxDynamicSharedMemorySize, SMEM);

    // Layer plan (ping-pong so no kernel reads and writes the same buffer):
    //   L0: h=x    agg=buf0  o1=buf1  o2=buf0
    //   L1: h=buf0 agg=buf1  o1=buf0  o2=buf1
    //   L2: h=buf1 agg=buf0  o1=buf1  o2=out
    const float* hs[3]  = {x, buf0, buf1};
    float* aggs[3]      = {buf0, buf1, buf0};
    float* o1s[3]       = {buf1, buf0, buf1};
    float* o2s[3]       = {buf0, buf1, out};

    int n4 = N * (DIM / 4);
    dim3 cpGrid((n4 + 255) / 256);
    long long scThreads = (long long)E * 32;
    dim3 scGrid((unsigned)((scThreads + 255) / 256));
    dim3 gmGrid((N + 63) / 64);

    for (int i = 0; i < 3; i++) {
        const float* h = hs[i];
        float* agg = aggs[i];

        copy_kernel<<<cpGrid, 256>>>(h, agg, n4);
        scatter_kernel<<<scGrid, 256>>>(h, src, dst, agg, E);

        gemm_bn_relu_kernel<<<gmGrid, 256, SMEM>>>(
            agg, W1 + (size_t)i * DIM * DIM, b1 + (size_t)i * DIM,
            g  + (size_t)(2 * i + 0) * DIM, be + (size_t)(2 * i + 0) * DIM,
            rm + (size_t)(2 * i + 0) * DIM, rv + (size_t)(2 * i + 0) * DIM,
            o1s[i], N);

        gemm_bn_relu_kernel<<<gmGrid, 256, SMEM>>>(
            o1s[i], W2 + (size_t)i * DIM * DIM, b2 + (size_t)i * DIM,
            g  + (size_t)(2 * i + 1) * DIM, be + (size_t)(2 * i + 1) * DIM,
            rm + (size_t)(2 * i + 1) * DIM, rv + (size_t)(2 * i + 1) * DIM,
            o2s[i], N);
    }
}

// round 2
// speedup vs baseline: 1.8363x; 1.8363x over previous
#include <cuda_runtime.h>
#include <cuda_bf16.h>

#define DIM 128
#define NMAX 50000
#define EMAX 800000
#define BN_EPS 1e-5f

// Scratch (allocation-free: __device__ globals)
__device__ float g_buf0[NMAX * DIM];
__device__ float g_buf1[NMAX * DIM];
__device__ int   g_deg[NMAX + 1];
__device__ int   g_off[NMAX + 1];
__device__ int   g_cur[NMAX];
__device__ int   g_csr[EMAX];

// ---------------------------------------------------------------------------
// CSR build step 1: zero degree counters
// ---------------------------------------------------------------------------
__global__ void zero_deg_kernel(int* __restrict__ deg, int n) {
    int i = blockIdx.x * blockDim.x + threadIdx.x;
    if (i <= n) deg[i] = 0;
}

// step 2: histogram of in-degrees
__global__ void hist_kernel(const int* __restrict__ dst, int* __restrict__ deg, int e) {
    int i = blockIdx.x * blockDim.x + threadIdx.x;
    if (i < e) atomicAdd(&deg[dst[i]], 1);
}

// step 3: single-block exclusive prefix scan over n degrees -> off, cursor
__global__ void scan_kernel(const int* __restrict__ deg, int* __restrict__ off,
                            int* __restrict__ cur, int n) {
    __shared__ int sh[1024];
    __shared__ int carry;
    int tid = threadIdx.x;
    if (tid == 0) carry = 0;
    __syncthreads();
    for (int base = 0; base < n; base += 1024) {
        int i = base + tid;
        int v = (i < n) ? deg[i] : 0;
        sh[tid] = v;
        __syncthreads();
        // Hillis-Steele inclusive scan
        #pragma unroll
        for (int s = 1; s < 1024; s <<= 1) {
            int t = (tid >= s) ? sh[tid - s] : 0;
            __syncthreads();
            sh[tid] += t;
            __syncthreads();
        }
        int incl = sh[tid];
        int excl = incl - v;
        if (i < n) {
            int o = carry + excl;
            off[i] = o;
            cur[i] = o;
        }
        __syncthreads();
        if (tid == 1023) carry += sh[1023];
        __syncthreads();
    }
    if (tid == 0) off[n] = carry;
}

// step 4: fill CSR edge lists (order within a list is arbitrary)
__global__ void fill_kernel(const int* __restrict__ src, const int* __restrict__ dst,
                            int* __restrict__ cur, int* __restrict__ csr, int e) {
    int i = blockIdx.x * blockDim.x + threadIdx.x;
    if (i < e) {
        int pos = atomicAdd(&cur[dst[i]], 1);
        csr[pos] = src[i];
    }
}

// ---------------------------------------------------------------------------
// Fused GIN aggregation (gather form, no atomics):
//   out[n] = h[n] + sum_{s in CSR[n]} h[s]
// One warp per node; lane handles 4 consecutive floats (float4).
// 4-way neighbor unroll for memory-level parallelism.
// ---------------------------------------------------------------------------
__global__ void gather_kernel(const float* __restrict__ h,
                              const int* __restrict__ off,
                              const int* __restrict__ csr,
                              float* __restrict__ out, int n) {
    int warp = (blockIdx.x * blockDim.x + threadIdx.x) >> 5;
    int lane = threadIdx.x & 31;
    if (warp >= n) return;
    int beg = off[warp];
    int end = off[warp + 1];
    size_t c = (size_t)lane * 4;

    float4 acc = *(const float4*)(h + (size_t)warp * DIM + c);

    int i = beg;
    for (; i + 4 <= end; i += 4) {
        int s0 = __ldg(csr + i);
        int s1 = __ldg(csr + i + 1);
        int s2 = __ldg(csr + i + 2);
        int s3 = __ldg(csr + i + 3);
        float4 a = *(const float4*)(h + (size_t)s0 * DIM + c);
        float4 b = *(const float4*)(h + (size_t)s1 * DIM + c);
        float4 d = *(const float4*)(h + (size_t)s2 * DIM + c);
        float4 f = *(const float4*)(h + (size_t)s3 * DIM + c);
        acc.x += a.x + b.x + d.x + f.x;
        acc.y += a.y + b.y + d.y + f.y;
        acc.z += a.z + b.z + d.z + f.z;
        acc.w += a.w + b.w + d.w + f.w;
    }
    for (; i < end; i++) {
        int s = __ldg(csr + i);
        float4 a = *(const float4*)(h + (size_t)s * DIM + c);
        acc.x += a.x; acc.y += a.y; acc.z += a.z; acc.w += a.w;
    }
    *(float4*)(out + (size_t)warp * DIM + c) = acc;
}

// ---------------------------------------------------------------------------
// Fused GEMM + bias + BatchNorm(eval) + ReLU (same as R1)
// ---------------------------------------------------------------------------
__global__ void __launch_bounds__(256, 2)
gemm_bn_relu_kernel(const float* __restrict__ A,
                    const float* __restrict__ W,
                    const float* __restrict__ bias,
                    const float* __restrict__ gamma,
                    const float* __restrict__ beta,
                    const float* __restrict__ mean,
                    const float* __restrict__ var,
                    float* __restrict__ out, int nrows) {
    extern __shared__ float sm[];
    float* Ws = sm;               // 128*128
    float* Hs = sm + DIM * DIM;   // 64*128

    int tid = threadIdx.x;

    const float4* W4 = (const float4*)W;
    float4* Ws4 = (float4*)Ws;
#pragma unroll
    for (int i = tid; i < DIM * (DIM / 4); i += 256) {
        Ws4[i] = W4[i];
    }

    int row0 = blockIdx.x * 64;
    float4* Hs4 = (float4*)Hs;
    for (int i = tid; i < 64 * (DIM / 4); i += 256) {
        int r = i >> 5;
        int row = row0 + r;
        float4 v = make_float4(0.f, 0.f, 0.f, 0.f);
        if (row < nrows) {
            v = ((const float4*)(A + (size_t)row * DIM))[i & 31];
        }
        Hs4[i] = v;
    }
    __syncthreads();

    int col = tid & 127;
    int half = tid >> 7;
    const float* hb = Hs + half * 32 * DIM;

    float acc[32];
#pragma unroll
    for (int r = 0; r < 32; r++) acc[r] = 0.f;

#pragma unroll 8
    for (int k = 0; k < DIM; k += 4) {
        float w0 = Ws[(k + 0) * DIM + col];
        float w1 = Ws[(k + 1) * DIM + col];
        float w2 = Ws[(k + 2) * DIM + col];
        float w3 = Ws[(k + 3) * DIM + col];
#pragma unroll
        for (int r = 0; r < 32; r++) {
            float4 h4 = *(const float4*)(hb + r * DIM + k);
            acc[r] = fmaf(h4.w, w3, fmaf(h4.z, w2, fmaf(h4.y, w1, fmaf(h4.x, w0, acc[r]))));
        }
    }

    float b  = bias[col];
    float sc = gamma[col] * rsqrtf(var[col] + BN_EPS);
    float sh = beta[col] - mean[col] * sc;
    int rbase = row0 + half * 32;
#pragma unroll
    for (int r = 0; r < 32; r++) {
        int row = rbase + r;
        if (row < nrows) {
            float z = (acc[r] + b) * sc + sh;
            out[(size_t)row * DIM + col] = fmaxf(z, 0.f);
        }
    }
}

// ---------------------------------------------------------------------------
// Launch
// Inputs: x[N,128], edge_index[2,E], W1[3,128,128], b1[3,128],
// W2[3,128,128], b2[3,128], g[3,2,128], be[3,2,128], rm[3,2,128], rv[3,2,128]
// ---------------------------------------------------------------------------
extern "C" void kernel_launch(void* const* d_in, const int* in_sizes, int n_in,
                              void* d_out, int out_size) {
    const float* x   = (const float*)d_in[0];
    const int*   ei  = (const int*)d_in[1];
    const float* W1  = (const float*)d_in[2];
    const float* b1  = (const float*)d_in[3];
    const float* W2  = (const float*)d_in[4];
    const float* b2  = (const float*)d_in[5];
    const float* g   = (const float*)d_in[6];
    const float* be  = (const float*)d_in[7];
    const float* rm  = (const float*)d_in[8];
    const float* rv  = (const float*)d_in[9];

    int N = in_sizes[0] / DIM;
    int E = in_sizes[1] / 2;
    const int* src = ei;
    const int* dst = ei + E;

    float* out = (float*)d_out;

    float* buf0; float* buf1;
    int *deg, *off, *cur, *csr;
    cudaGetSymbolAddress((void**)&buf0, g_buf0);
    cudaGetSymbolAddress((void**)&buf1, g_buf1);
    cudaGetSymbolAddress((void**)&deg, g_deg);
    cudaGetSymbolAddress((void**)&off, g_off);
    cudaGetSymbolAddress((void**)&cur, g_cur);
    cudaGetSymbolAddress((void**)&csr, g_csr);

    const int SMEM = (DIM * DIM + 64 * DIM) * (int)sizeof(float);  // 96 KB
    cudaFuncSetAttribute(gemm_bn_relu_kernel,
                         cudaFuncAttributeMaxDynamicSharedMemorySize, SMEM);

    // ---- Build CSR (once per launch) ----
    zero_deg_kernel<<<(N + 256) / 256, 256>>>(deg, N);
    hist_kernel<<<(E + 255) / 256, 256>>>(dst, deg, E);
    scan_kernel<<<1, 1024>>>(deg, off, cur, N);
    fill_kernel<<<(E + 255) / 256, 256>>>(src, dst, cur, csr, E);

    // ---- Layers ----
    // L0: h=x    agg=buf0  o1=buf1  o2=buf0
    // L1: h=buf0 agg=buf1  o1=buf0  o2=buf1
    // L2: h=buf1 agg=buf0  o1=buf1  o2=out
    const float* hs[3]  = {x, buf0, buf1};
    float* aggs[3]      = {buf0, buf1, buf0};
    float* o1s[3]       = {buf1, buf0, buf1};
    float* o2s[3]       = {buf0, buf1, out};

    dim3 gaGrid((N * 32 + 255) / 256);
    dim3 gmGrid((N + 63) / 64);

    for (int i = 0; i < 3; i++) {
        gather_kernel<<<gaGrid, 256>>>(hs[i], off, csr, aggs[i], N);

        gemm_bn_relu_kernel<<<gmGrid, 256, SMEM>>>(
            aggs[i], W1 + (size_t)i * DIM * DIM, b1 + (size_t)i * DIM,
            g  + (size_t)(2 * i + 0) * DIM, be + (size_t)(2 * i + 0) * DIM,
            rm + (size_t)(2 * i + 0) * DIM, rv + (size_t)(2 * i + 0) * DIM,
            o1s[i], N);

        gemm_bn_relu_kernel<<<gmGrid, 256, SMEM>>>(
            o1s[i], W2 + (size_t)i * DIM * DIM, b2 + (size_t)i * DIM,
            g  + (size_t)(2 * i + 1) * DIM, be + (size_t)(2 * i + 1) * DIM,
            rm + (size_t)(2 * i + 1) * DIM, rv + (size_t)(2 * i + 1) * DIM,
            o2s[i], N);
    }
}

// round 6
// speedup vs baseline: 3.1123x; 1.6948x over previous
#include <cuda_runtime.h>
#include <cuda_bf16.h>
#include <mma.h>
#include <cstdint>

using namespace nvcuda;

#define DIM 128
#define NMAX 50000
#define EMAX 800000
#define BN_EPS 1e-5f

// ---------------- scratch (allocation-free) ----------------
__device__ float g_buf0[NMAX * DIM];
__device__ float g_buf1[NMAX * DIM];
__device__ int   g_deg[NMAX + 1];
__device__ int   g_off[NMAX + 1];
__device__ int   g_cur[NMAX];
__device__ int   g_csr[EMAX];
__device__ __nv_bfloat16 g_wt_hi[6 * DIM * DIM];  // transposed: [w][j][k]
__device__ __nv_bfloat16 g_wt_lo[6 * DIM * DIM];

// ---------------- CSR build ----------------
__global__ void zero_deg_kernel(int* __restrict__ deg, int n) {
    int i = blockIdx.x * blockDim.x + threadIdx.x;
    if (i <= n) deg[i] = 0;
}

__global__ void hist_kernel(const int* __restrict__ dst, int* __restrict__ deg, int e) {
    int i = blockIdx.x * blockDim.x + threadIdx.x;
    if (i < e) atomicAdd(&deg[dst[i]], 1);
}

__global__ void scan_kernel(const int* __restrict__ deg, int* __restrict__ off,
                            int* __restrict__ cur, int n) {
    __shared__ int sh[1024];
    __shared__ int carry;
    int tid = threadIdx.x;
    if (tid == 0) carry = 0;
    __syncthreads();
    for (int base = 0; base < n; base += 1024) {
        int i = base + tid;
        int v = (i < n) ? deg[i] : 0;
        sh[tid] = v;
        __syncthreads();
#pragma unroll
        for (int s = 1; s < 1024; s <<= 1) {
            int t = (tid >= s) ? sh[tid - s] : 0;
            __syncthreads();
            sh[tid] += t;
            __syncthreads();
        }
        int excl = sh[tid] - v;
        if (i < n) {
            int o = carry + excl;
            off[i] = o;
            cur[i] = o;
        }
        __syncthreads();
        if (tid == 1023) carry += sh[1023];
        __syncthreads();
    }
    if (tid == 0) off[n] = carry;
}

__global__ void fill_kernel(const int* __restrict__ src, const int* __restrict__ dst,
                            int* __restrict__ cur, int* __restrict__ csr, int e) {
    int i = blockIdx.x * blockDim.x + threadIdx.x;
    if (i < e) {
        int pos = atomicAdd(&cur[dst[i]], 1);
        csr[pos] = src[i];
    }
}

// ---------------- weight prep: transpose + bf16 hi/lo split ----------------
// g_wt_hi[w][j][k] = bf16(W[k][j]), g_wt_lo = bf16(residual); w = 2*layer + (0:W1, 1:W2)
__global__ void prep_w_kernel(const float* __restrict__ W1, const float* __restrict__ W2) {
    int idx = blockIdx.x * blockDim.x + threadIdx.x;
    if (idx >= 6 * DIM * DIM) return;
    int w = idx >> 14;
    int r = idx & 16383;
    int k = r >> 7;
    int j = r & 127;
    const float* srcm = (w & 1) ? W2 : W1;
    float v = srcm[((size_t)(w >> 1) << 14) + (k << 7) + j];
    __nv_bfloat16 hi = __float2bfloat16(v);
    __nv_bfloat16 lo = __float2bfloat16(v - __bfloat162float(hi));
    int dst = (w << 14) + (j << 7) + k;
    g_wt_hi[dst] = hi;
    g_wt_lo[dst] = lo;
}

// ---------------- gather: out[n] = h[n] + sum h[csr[n]] ----------------
__global__ void gather_kernel(const float* __restrict__ h,
                              const int* __restrict__ off,
                              const int* __restrict__ csr,
                              float* __restrict__ out, int n) {
    int warp = (blockIdx.x * blockDim.x + threadIdx.x) >> 5;
    int lane = threadIdx.x & 31;
    if (warp >= n) return;
    int beg = off[warp];
    int end = off[warp + 1];
    size_t c = (size_t)lane * 4;

    float4 acc = *(const float4*)(h + (size_t)warp * DIM + c);
    int i = beg;
    for (; i + 4 <= end; i += 4) {
        int s0 = __ldg(csr + i);
        int s1 = __ldg(csr + i + 1);
        int s2 = __ldg(csr + i + 2);
        int s3 = __ldg(csr + i + 3);
        float4 a = *(const float4*)(h + (size_t)s0 * DIM + c);
        float4 b = *(const float4*)(h + (size_t)s1 * DIM + c);
        float4 d = *(const float4*)(h + (size_t)s2 * DIM + c);
        float4 f = *(const float4*)(h + (size_t)s3 * DIM + c);
        acc.x += a.x + b.x + d.x + f.x;
        acc.y += a.y + b.y + d.y + f.y;
        acc.z += a.z + b.z + d.z + f.z;
        acc.w += a.w + b.w + d.w + f.w;
    }
    for (; i < end; i++) {
        int s = __ldg(csr + i);
        float4 a = *(const float4*)(h + (size_t)s * DIM + c);
        acc.x += a.x; acc.y += a.y; acc.z += a.z; acc.w += a.w;
    }
    *(float4*)(out + (size_t)warp * DIM + c) = acc;
}

// ---------------- wmma bf16x3 GEMM + bias + BN + ReLU ----------------
// out[row,j] = relu((sum_k A[row,k]*Wt[j,k] + bias[j]) * sc[j] + sh[j])
// bf16x3: D = hiA*hiB + hiA*loB + loA*hiB, fp32 accumulation (HMMA fallback path).
#define LDA 136                              // padded row length (bf16 elems)
#define A_BYTES (128 * LDA * 2)              // 34816
#define OFF_AHI 0
#define OFF_ALO (OFF_AHI + A_BYTES)
#define OFF_BHI (OFF_ALO + A_BYTES)
#define OFF_BLO (OFF_BHI + A_BYTES)
#define SMEM_TOTAL (OFF_BLO + A_BYTES)       // 139264 B
#define OFF_STG OFF_BHI                      // epilogue staging reuses B (69632 B)

__global__ void __launch_bounds__(256, 1)
gemm_wmma_kernel(const float* __restrict__ A,
                 const __nv_bfloat16* __restrict__ Bt_hi,
                 const __nv_bfloat16* __restrict__ Bt_lo,
                 const float* __restrict__ bias,
                 const float* __restrict__ gamma,
                 const float* __restrict__ beta,
                 const float* __restrict__ mean,
                 const float* __restrict__ var,
                 float* __restrict__ out, int nrows) {
    extern __shared__ char smem[];
    __nv_bfloat16* Ahi = (__nv_bfloat16*)(smem + OFF_AHI);
    __nv_bfloat16* Alo = (__nv_bfloat16*)(smem + OFF_ALO);
    __nv_bfloat16* Bhi = (__nv_bfloat16*)(smem + OFF_BHI);
    __nv_bfloat16* Blo = (__nv_bfloat16*)(smem + OFF_BLO);

    int tid = threadIdx.x;
    int wid = tid >> 5;
    int lane = tid & 31;
    int row0 = blockIdx.x * 128;

    // stage B (pre-split bf16 [j][k]) into padded smem rows
    {
        const uint4* shi = (const uint4*)Bt_hi;
        const uint4* slo = (const uint4*)Bt_lo;
#pragma unroll
        for (int i = tid; i < 2048; i += 256) {
            int j = i >> 4;
            int k8 = (i & 15) << 3;
            uint32_t o = (uint32_t)(j * LDA + k8);
            *(uint4*)(Bhi + o) = shi[i];
            *(uint4*)(Blo + o) = slo[i];
        }
    }
    // stage A with fp32 -> bf16 hi/lo split
    {
#pragma unroll
        for (int i = tid; i < 4096; i += 256) {
            int r = i >> 5;
            int k4 = (i & 31) << 2;
            float4 v = make_float4(0.f, 0.f, 0.f, 0.f);
            if (row0 + r < nrows)
                v = ((const float4*)(A + (size_t)(row0 + r) * DIM))[i & 31];
            __nv_bfloat16 h0 = __float2bfloat16(v.x), h1 = __float2bfloat16(v.y);
            __nv_bfloat16 h2 = __float2bfloat16(v.z), h3 = __float2bfloat16(v.w);
            __nv_bfloat16 l0 = __float2bfloat16(v.x - __bfloat162float(h0));
            __nv_bfloat16 l1 = __float2bfloat16(v.y - __bfloat162float(h1));
            __nv_bfloat16 l2 = __float2bfloat16(v.z - __bfloat162float(h2));
            __nv_bfloat16 l3 = __float2bfloat16(v.w - __bfloat162float(h3));
            __nv_bfloat162 hA(h0, h1), hB(h2, h3), lA(l0, l1), lB(l2, l3);
            uint32_t o = (uint32_t)(r * LDA + k4);
            *(uint2*)(Ahi + o) = make_uint2(*(uint32_t*)&hA, *(uint32_t*)&hB);
            *(uint2*)(Alo + o) = make_uint2(*(uint32_t*)&lA, *(uint32_t*)&lB);
        }
    }
    __syncthreads();

    // mainloop: warp wid computes rows [wid*16, wid*16+16) x all 128 cols
    wmma::fragment<wmma::accumulator, 16, 16, 16, float> c[8];
#pragma unroll
    for (int n = 0; n < 8; n++) wmma::fill_fragment(c[n], 0.0f);

    const __nv_bfloat16* arow_hi = Ahi + wid * 16 * LDA;
    const __nv_bfloat16* arow_lo = Alo + wid * 16 * LDA;

#pragma unroll
    for (int k0 = 0; k0 < 8; k0++) {
        wmma::fragment<wmma::matrix_a, 16, 16, 16, __nv_bfloat16, wmma::row_major> ahi, alo;
        wmma::load_matrix_sync(ahi, arow_hi + k0 * 16, LDA);
        wmma::load_matrix_sync(alo, arow_lo + k0 * 16, LDA);
#pragma unroll
        for (int n = 0; n < 8; n++) {
            wmma::fragment<wmma::matrix_b, 16, 16, 16, __nv_bfloat16, wmma::col_major> bhi, blo;
            // B[k][j] stored as Bt[j*LDA + k] => col_major with ld = LDA
            wmma::load_matrix_sync(bhi, Bhi + n * 16 * LDA + k0 * 16, LDA);
            wmma::load_matrix_sync(blo, Blo + n * 16 * LDA + k0 * 16, LDA);
            wmma::mma_sync(c[n], ahi, bhi, c[n]);
            wmma::mma_sync(c[n], ahi, blo, c[n]);
            wmma::mma_sync(c[n], alo, bhi, c[n]);
        }
    }

    __syncthreads();  // everyone done reading B before staging reuses it

    // stage accumulators to smem (per-warp 16 x 136-float region), then
    // BN+ReLU + coalesced float4 stores
    float* stg = (float*)(smem + OFF_STG) + wid * (16 * LDA);
#pragma unroll
    for (int n = 0; n < 8; n++)
        wmma::store_matrix_sync(stg + n * 16, c[n], LDA, wmma::mem_row_major);

    int col = lane * 4;
    float4 gm = *(const float4*)(gamma + col);
    float4 vr = *(const float4*)(var + col);
    float4 bt = *(const float4*)(beta + col);
    float4 mn = *(const float4*)(mean + col);
    float4 bs = *(const float4*)(bias + col);
    float4 sc4, sh4;
    sc4.x = gm.x * rsqrtf(vr.x + BN_EPS);
    sc4.y = gm.y * rsqrtf(vr.y + BN_EPS);
    sc4.z = gm.z * rsqrtf(vr.z + BN_EPS);
    sc4.w = gm.w * rsqrtf(vr.w + BN_EPS);
    sh4.x = bt.x - mn.x * sc4.x + bs.x * sc4.x;
    sh4.y = bt.y - mn.y * sc4.y + bs.y * sc4.y;
    sh4.z = bt.z - mn.z * sc4.z + bs.z * sc4.z;
    sh4.w = bt.w - mn.w * sc4.w + bs.w * sc4.w;

    int rbase = row0 + wid * 16;
#pragma unroll
    for (int r = 0; r < 16; r++) {
        int row = rbase + r;
        if (row < nrows) {
            float4 v = *(const float4*)(stg + r * LDA + col);
            v.x = fmaxf(fmaf(v.x, sc4.x, sh4.x), 0.f);
            v.y = fmaxf(fmaf(v.y, sc4.y, sh4.y), 0.f);
            v.z = fmaxf(fmaf(v.z, sc4.z, sh4.z), 0.f);
            v.w = fmaxf(fmaf(v.w, sc4.w, sh4.w), 0.f);
            *(float4*)(out + (size_t)row * DIM + col) = v;
        }
    }
}

// ---------------- launch ----------------
extern "C" void kernel_launch(void* const* d_in, const int* in_sizes, int n_in,
                              void* d_out, int out_size) {
    const float* x  = (const float*)d_in[0];
    const int*   ei = (const int*)d_in[1];
    const float* W1 = (const float*)d_in[2];
    const float* b1 = (const float*)d_in[3];
    const float* W2 = (const float*)d_in[4];
    const float* b2 = (const float*)d_in[5];
    const float* g  = (const float*)d_in[6];
    const float* be = (const float*)d_in[7];
    const float* rm = (const float*)d_in[8];
    const float* rv = (const float*)d_in[9];

    int N = in_sizes[0] / DIM;
    int E = in_sizes[1] / 2;
    const int* src = ei;
    const int* dst = ei + E;
    float* out = (float*)d_out;

    float *buf0, *buf1;
    int *deg, *off, *cur, *csr;
    __nv_bfloat16 *wth, *wtl;
    cudaGetSymbolAddress((void**)&buf0, g_buf0);
    cudaGetSymbolAddress((void**)&buf1, g_buf1);
    cudaGetSymbolAddress((void**)&deg, g_deg);
    cudaGetSymbolAddress((void**)&off, g_off);
    cudaGetSymbolAddress((void**)&cur, g_cur);
    cudaGetSymbolAddress((void**)&csr, g_csr);
    cudaGetSymbolAddress((void**)&wth, g_wt_hi);
    cudaGetSymbolAddress((void**)&wtl, g_wt_lo);

    cudaFuncSetAttribute(gemm_wmma_kernel,
                         cudaFuncAttributeMaxDynamicSharedMemorySize, SMEM_TOTAL);

    // weight prep + CSR build
    prep_w_kernel<<<(6 * DIM * DIM + 255) / 256, 256>>>(W1, W2);
    zero_deg_kernel<<<(N + 256) / 256, 256>>>(deg, N);
    hist_kernel<<<(E + 255) / 256, 256>>>(dst, deg, E);
    scan_kernel<<<1, 1024>>>(deg, off, cur, N);
    fill_kernel<<<(E + 255) / 256, 256>>>(src, dst, cur, csr, E);

    // layers (ping-pong)
    const float* hs[3] = {x, buf0, buf1};
    float* aggs[3]     = {buf0, buf1, buf0};
    float* o1s[3]      = {buf1, buf0, buf1};
    float* o2s[3]      = {buf0, buf1, out};

    dim3 gaGrid((N * 32 + 255) / 256);
    dim3 gmGrid((N + 127) / 128);

    for (int i = 0; i < 3; i++) {
        gather_kernel<<<gaGrid, 256>>>(hs[i], off, csr, aggs[i], N);

        int w1i = 2 * i, w2i = 2 * i + 1;
        gemm_wmma_kernel<<<gmGrid, 256, SMEM_TOTAL>>>(
            aggs[i], wth + (size_t)w1i * DIM * DIM, wtl + (size_t)w1i * DIM * DIM,
            b1 + (size_t)i * DIM,
            g  + (size_t)(2 * i + 0) * DIM, be + (size_t)(2 * i + 0) * DIM,
            rm + (size_t)(2 * i + 0) * DIM, rv + (size_t)(2 * i + 0) * DIM,
            o1s[i], N);

        gemm_wmma_kernel<<<gmGrid, 256, SMEM_TOTAL>>>(
            o1s[i], wth + (size_t)w2i * DIM * DIM, wtl + (size_t)w2i * DIM * DIM,
            b2 + (size_t)i * DIM,
            g  + (size_t)(2 * i + 1) * DIM, be + (size_t)(2 * i + 1) * DIM,
            rm + (size_t)(2 * i + 1) * DIM, rv + (size_t)(2 * i + 1) * DIM,
            o2s[i], N);
    }
}